// round 14
// baseline (speedup 1.0000x reference)
#include <cuda_runtime.h>
#include <cuda_bf16.h>

// Nearest-codeword quantization, uniform sorted 16-entry codebook.
// out[i] = argmin_c |x[i] - c|, tie toward the LOWER codeword.
//
// R14 = R13 (single warp-vote per 16 elements, coalesced block-strided
// ILP=4, front-batched LDG.128, uninterrupted STG.128 burst) computing
// IN PLACE: results overwrite vv[] so only 16 payload regs stay live across
// the vote (R13 held vv+rr = 32 -> 64 regs, occ 39.7%). The rare exact path
// (~10% of warp-iterations) reloads x from global — those lines are freshly
// touched and L2/L1-resident, so the reload is noise.
//
// Hot path per element (branchless): t = fma(x,inv,b0); tc = clamp(t,0,15);
// tr = rintf(tc); val = fma(tr,step,c0); maxd = fmax(maxd,|tc-tr|).
// Exact path: true codebook values via __ldg, reference tie-break
// (|x-lo| <= |x-hi| -> lo). val is <=1 ulp from the stored linspace
// codeword (rel_err ~7e-8, tol 1e-3).

#define K_CB 16

__global__ void __launch_bounds__(256)
quant_uniform_kernel(const float4* __restrict__ x,
                     const float*  __restrict__ cb,
                     float4* __restrict__ out,
                     int n4)
{
    const float c0 = __ldg(cb);
    const float cK = __ldg(cb + K_CB - 1);
    const float step     = (cK - c0) * (1.0f / (float)(K_CB - 1));
    const float inv_step = (float)(K_CB - 1) / (cK - c0);
    const float b0 = -c0 * inv_step;
    const float TH = 0.5f - 1e-4f;      // guard threshold in index space

    const int tid  = threadIdx.x;
    const int bdim = blockDim.x;                  // 256
    const int base = blockIdx.x * (bdim * 4) + tid;

    if (base + 3 * bdim < n4) {
        // 4 fully-coalesced independent LDG.128, front-batched.
        float4 vv[4];
        vv[0] = x[base + 0 * bdim];
        vv[1] = x[base + 1 * bdim];
        vv[2] = x[base + 2 * bdim];
        vv[3] = x[base + 3 * bdim];

        float maxd = 0.0f;

        // Compute IN PLACE: vv[u] becomes the result.
#pragma unroll
        for (int u = 0; u < 4; u++) {
            float* vp = reinterpret_cast<float*>(&vv[u]);
#pragma unroll
            for (int j = 0; j < 4; j++) {
                float xv = vp[j];
                float t  = fmaf(xv, inv_step, b0);
                float tc = fminf(fmaxf(t, 0.0f), (float)(K_CB - 1));
                float tr = rintf(tc);
                vp[j] = fmaf(tr, step, c0);
                maxd = fmaxf(maxd, fabsf(tc - tr));   // FMNMX with |.|
            }
        }

        // ONE vote per 16 elements. Rare path reloads x (L2/L1-resident).
        if (__any_sync(0xFFFFFFFFu, maxd >= TH)) {
#pragma unroll
            for (int u = 0; u < 4; u++) {
                float4 v = x[base + u * bdim];      // re-read originals
                const float* vp = reinterpret_cast<const float*>(&v);
                float* rp = reinterpret_cast<float*>(&vv[u]);
#pragma unroll
                for (int j = 0; j < 4; j++) {
                    float xv = vp[j];
                    float t  = fmaf(xv, inv_step, b0);
                    int k = min(max(__float2int_rd(t), 0), K_CB - 2);
                    float lo = __ldg(cb + k);
                    float hi = __ldg(cb + k + 1);
                    rp[j] = (fabsf(xv - lo) <= fabsf(xv - hi)) ? lo : hi;
                }
            }
        }

        // Uninterrupted store burst.
        out[base + 0 * bdim] = vv[0];
        out[base + 1 * bdim] = vv[1];
        out[base + 2 * bdim] = vv[2];
        out[base + 3 * bdim] = vv[3];
    } else {
        // Tail (not taken for 8192x8192): always-exact scalar path.
        for (int u = 0; u < 4; u++) {
            int idx = base + u * bdim;
            if (idx >= n4) break;
            float4 v = x[idx];
            float4 r;
            const float* vp = reinterpret_cast<const float*>(&v);
            float* rp = reinterpret_cast<float*>(&r);
#pragma unroll
            for (int j = 0; j < 4; j++) {
                float xv = vp[j];
                float t  = fmaf(xv, inv_step, b0);
                int k = min(max(__float2int_rd(t), 0), K_CB - 2);
                float lo = __ldg(cb + k);
                float hi = __ldg(cb + k + 1);
                rp[j] = (fabsf(xv - lo) <= fabsf(xv - hi)) ? lo : hi;
            }
            out[idx] = r;
        }
    }
}

extern "C" void kernel_launch(void* const* d_in, const int* in_sizes, int n_in,
                              void* d_out, int out_size)
{
    const float* x  = (const float*)d_in[0];
    const float* cb = (const float*)d_in[1];
    float* out = (float*)d_out;

    int n  = in_sizes[0];         // 8192*8192 = 67,108,864
    int n4 = n >> 2;              // 16,777,216 float4

    const int threads = 256;
    const int per_block = threads * 4;                 // 1024 float4 / block
    int blocks = (n4 + per_block - 1) / per_block;     // 16384

    quant_uniform_kernel<<<blocks, threads>>>(
        (const float4*)x, cb, (float4*)out, n4);
}

// round 15
// speedup vs baseline: 1.0994x; 1.0994x over previous
#include <cuda_runtime.h>
#include <cuda_bf16.h>

// Nearest-codeword quantization, uniform sorted 16-entry codebook.
// out[i] = argmin_c |x[i] - c|, tie toward the LOWER codeword.
//
// R15 = R13 (best structure: coalesced block-strided ILP=4, front-batched
// LDG.128, ONE warp-vote per 16 elements, uninterrupted STG.128 burst,
// separate rr[] — the known-good codegen) with block size 128 instead of
// 256: at 64 regs, 128-thread CTAs pack 8/SM (vs 3-4), finer wave-balance
// granularity across 152 SMs. R14's in-place variant spilled (L1 58%) and
// is reverted.
//
// Hot path per element (branchless): t = fma(x,inv,b0); tc = clamp(t,0,15);
// tr = rintf(tc); val = fma(tr,step,c0); maxd = fmax(maxd,|tc-tr|).
// If any lane of the warp is within EPS=1e-4 (index space) of a midpoint,
// the iteration is recomputed exactly against the TRUE codebook values
// (__ldg, reference tie-break |x-lo| <= |x-hi| -> lo). val is <=1 ulp from
// the stored linspace codeword (rel_err ~7e-8, tol 1e-3).

#define K_CB 16

__global__ void __launch_bounds__(128)
quant_uniform_kernel(const float4* __restrict__ x,
                     const float*  __restrict__ cb,
                     float4* __restrict__ out,
                     int n4)
{
    const float c0 = __ldg(cb);
    const float cK = __ldg(cb + K_CB - 1);
    const float step     = (cK - c0) * (1.0f / (float)(K_CB - 1));
    const float inv_step = (float)(K_CB - 1) / (cK - c0);
    const float b0 = -c0 * inv_step;
    const float TH = 0.5f - 1e-4f;      // guard threshold in index space

    const int tid  = threadIdx.x;
    const int bdim = blockDim.x;                  // 128
    const int base = blockIdx.x * (bdim * 4) + tid;

    if (base + 3 * bdim < n4) {
        // 4 fully-coalesced independent LDG.128, front-batched.
        float4 vv[4];
        vv[0] = x[base + 0 * bdim];
        vv[1] = x[base + 1 * bdim];
        vv[2] = x[base + 2 * bdim];
        vv[3] = x[base + 3 * bdim];

        float4 rr[4];
        float maxd = 0.0f;

#pragma unroll
        for (int u = 0; u < 4; u++) {
            const float* vp = reinterpret_cast<const float*>(&vv[u]);
            float* rp = reinterpret_cast<float*>(&rr[u]);
#pragma unroll
            for (int j = 0; j < 4; j++) {
                float xv = vp[j];
                float t  = fmaf(xv, inv_step, b0);
                float tc = fminf(fmaxf(t, 0.0f), (float)(K_CB - 1));
                float tr = rintf(tc);
                rp[j] = fmaf(tr, step, c0);
                maxd = fmaxf(maxd, fabsf(tc - tr));   // FMNMX with |.|
            }
        }

        // ONE vote per 16 elements: does ANY lane need the exact path?
        if (__any_sync(0xFFFFFFFFu, maxd >= TH)) {
#pragma unroll
            for (int u = 0; u < 4; u++) {
                const float* vp = reinterpret_cast<const float*>(&vv[u]);
                float* rp = reinterpret_cast<float*>(&rr[u]);
#pragma unroll
                for (int j = 0; j < 4; j++) {
                    float xv = vp[j];
                    float t  = fmaf(xv, inv_step, b0);
                    int k = min(max(__float2int_rd(t), 0), K_CB - 2);
                    float lo = __ldg(cb + k);
                    float hi = __ldg(cb + k + 1);
                    rp[j] = (fabsf(xv - lo) <= fabsf(xv - hi)) ? lo : hi;
                }
            }
        }

        // Uninterrupted store burst.
        out[base + 0 * bdim] = rr[0];
        out[base + 1 * bdim] = rr[1];
        out[base + 2 * bdim] = rr[2];
        out[base + 3 * bdim] = rr[3];
    } else {
        // Tail (not taken for 8192x8192): always-exact scalar path.
        for (int u = 0; u < 4; u++) {
            int idx = base + u * bdim;
            if (idx >= n4) break;
            float4 v = x[idx];
            float4 r;
            const float* vp = reinterpret_cast<const float*>(&v);
            float* rp = reinterpret_cast<float*>(&r);
#pragma unroll
            for (int j = 0; j < 4; j++) {
                float xv = vp[j];
                float t  = fmaf(xv, inv_step, b0);
                int k = min(max(__float2int_rd(t), 0), K_CB - 2);
                float lo = __ldg(cb + k);
                float hi = __ldg(cb + k + 1);
                rp[j] = (fabsf(xv - lo) <= fabsf(xv - hi)) ? lo : hi;
            }
            out[idx] = r;
        }
    }
}

extern "C" void kernel_launch(void* const* d_in, const int* in_sizes, int n_in,
                              void* d_out, int out_size)
{
    const float* x  = (const float*)d_in[0];
    const float* cb = (const float*)d_in[1];
    float* out = (float*)d_out;

    int n  = in_sizes[0];         // 8192*8192 = 67,108,864
    int n4 = n >> 2;              // 16,777,216 float4

    const int threads = 128;
    const int per_block = threads * 4;                 // 512 float4 / block
    int blocks = (n4 + per_block - 1) / per_block;     // 32768

    quant_uniform_kernel<<<blocks, threads>>>(
        (const float4*)x, cb, (float4*)out, n4);
}

// round 16
// speedup vs baseline: 1.1270x; 1.0251x over previous
#include <cuda_runtime.h>
#include <cuda_bf16.h>

// Nearest-codeword quantization, uniform sorted 16-entry codebook.
// out[i] = argmin_c |x[i] - c|, tie toward the LOWER codeword.
//
// FINAL (== R13, the session best: 81.7us, 6.45 TB/s = 81.5% of spec HBM).
// Structure: coalesced block-strided ILP=4, 4 front-batched LDG.128, a
// branchless FMA-pipe hot path, ONE warp-vote per 16 elements for the rare
// exact path, then 4 uninterrupted STG.128.
//
// Session evidence that this is the roofline: occ 40-81%, MLP 2-8, .cs
// hints, persistent grid, block 128/256 all land at 6.28-6.45 TB/s; local/
// LDS codebook paths and per-element branches are strictly worse.
//
// Hot path per element: t = fma(x,inv,b0); tc = clamp(t,0,15);
// tr = rintf(tc); val = fma(tr,step,c0); maxd = fmax(maxd,|tc-tr|).
// If any lane of the warp is within EPS=1e-4 (index space) of a midpoint,
// the iteration is recomputed exactly against the TRUE codebook values
// (__ldg, reference tie-break |x-lo| <= |x-hi| -> lo). val is <=1 ulp from
// the stored linspace codeword (rel_err ~7e-8, tol 1e-3).

#define K_CB 16

__global__ void __launch_bounds__(256)
quant_uniform_kernel(const float4* __restrict__ x,
                     const float*  __restrict__ cb,
                     float4* __restrict__ out,
                     int n4)
{
    const float c0 = __ldg(cb);
    const float cK = __ldg(cb + K_CB - 1);
    const float step     = (cK - c0) * (1.0f / (float)(K_CB - 1));
    const float inv_step = (float)(K_CB - 1) / (cK - c0);
    const float b0 = -c0 * inv_step;
    const float TH = 0.5f - 1e-4f;      // guard threshold in index space

    const int tid  = threadIdx.x;
    const int bdim = blockDim.x;                  // 256
    const int base = blockIdx.x * (bdim * 4) + tid;

    if (base + 3 * bdim < n4) {
        // 4 fully-coalesced independent LDG.128, front-batched.
        float4 vv[4];
        vv[0] = x[base + 0 * bdim];
        vv[1] = x[base + 1 * bdim];
        vv[2] = x[base + 2 * bdim];
        vv[3] = x[base + 3 * bdim];

        float4 rr[4];
        float maxd = 0.0f;

#pragma unroll
        for (int u = 0; u < 4; u++) {
            const float* vp = reinterpret_cast<const float*>(&vv[u]);
            float* rp = reinterpret_cast<float*>(&rr[u]);
#pragma unroll
            for (int j = 0; j < 4; j++) {
                float xv = vp[j];
                float t  = fmaf(xv, inv_step, b0);
                float tc = fminf(fmaxf(t, 0.0f), (float)(K_CB - 1));
                float tr = rintf(tc);
                rp[j] = fmaf(tr, step, c0);
                maxd = fmaxf(maxd, fabsf(tc - tr));   // FMNMX with |.|
            }
        }

        // ONE vote per 16 elements: does ANY lane need the exact path?
        if (__any_sync(0xFFFFFFFFu, maxd >= TH)) {
#pragma unroll
            for (int u = 0; u < 4; u++) {
                const float* vp = reinterpret_cast<const float*>(&vv[u]);
                float* rp = reinterpret_cast<float*>(&rr[u]);
#pragma unroll
                for (int j = 0; j < 4; j++) {
                    float xv = vp[j];
                    float t  = fmaf(xv, inv_step, b0);
                    int k = min(max(__float2int_rd(t), 0), K_CB - 2);
                    float lo = __ldg(cb + k);
                    float hi = __ldg(cb + k + 1);
                    rp[j] = (fabsf(xv - lo) <= fabsf(xv - hi)) ? lo : hi;
                }
            }
        }

        // Uninterrupted store burst.
        out[base + 0 * bdim] = rr[0];
        out[base + 1 * bdim] = rr[1];
        out[base + 2 * bdim] = rr[2];
        out[base + 3 * bdim] = rr[3];
    } else {
        // Tail (not taken for 8192x8192): always-exact scalar path.
        for (int u = 0; u < 4; u++) {
            int idx = base + u * bdim;
            if (idx >= n4) break;
            float4 v = x[idx];
            float4 r;
            const float* vp = reinterpret_cast<const float*>(&v);
            float* rp = reinterpret_cast<float*>(&r);
#pragma unroll
            for (int j = 0; j < 4; j++) {
                float xv = vp[j];
                float t  = fmaf(xv, inv_step, b0);
                int k = min(max(__float2int_rd(t), 0), K_CB - 2);
                float lo = __ldg(cb + k);
                float hi = __ldg(cb + k + 1);
                rp[j] = (fabsf(xv - lo) <= fabsf(xv - hi)) ? lo : hi;
            }
            out[idx] = r;
        }
    }
}

extern "C" void kernel_launch(void* const* d_in, const int* in_sizes, int n_in,
                              void* d_out, int out_size)
{
    const float* x  = (const float*)d_in[0];
    const float* cb = (const float*)d_in[1];
    float* out = (float*)d_out;

    int n  = in_sizes[0];         // 8192*8192 = 67,108,864
    int n4 = n >> 2;              // 16,777,216 float4

    const int threads = 256;
    const int per_block = threads * 4;                 // 1024 float4 / block
    int blocks = (n4 + per_block - 1) / per_block;     // 16384

    quant_uniform_kernel<<<blocks, threads>>>(
        (const float4*)x, cb, (float4*)out, n4);
}